// round 4
// baseline (speedup 1.0000x reference)
#include <cuda_runtime.h>
#include <math.h>

#define NB 64
#define NT 512
#define NV 512
#define NH 256
#define NO 512
#define MR (NB * NT)   // 32768 rows

// Scratch (allocation-free rule: __device__ globals)
__device__ float g_xproj[(size_t)MR * NH];   // x@W_ih^T + b_ih + b_hh
__device__ float g_hidden[(size_t)MR * NH];  // min(relu(h),1)

typedef unsigned long long ull;

__device__ __forceinline__ ull fma2(ull a, ull b, ull c) {
    ull d;
    asm("fma.rn.f32x2 %0, %1, %2, %3;" : "=l"(d) : "l"(a), "l"(b), "l"(c));
    return d;
}
__device__ __forceinline__ ull pack2(float lo, float hi) {
    ull r;
    unsigned int l = __float_as_uint(lo), h = __float_as_uint(hi);
    asm("mov.b64 %0, {%1, %2};" : "=l"(r) : "r"(l), "r"(h));
    return r;
}
__device__ __forceinline__ float2 unpack2(ull v) {
    unsigned int l, h;
    asm("mov.b64 {%0, %1}, %2;" : "=r"(l), "=r"(h) : "l"(v));
    return make_float2(__uint_as_float(l), __uint_as_float(h));
}
__device__ __forceinline__ unsigned int s2u(const void* p) {
    return (unsigned int)__cvta_generic_to_shared(p);
}

// cluster-scope mbarrier wait (acquire.cluster — peer's release must pair)
#define WAIT_PARITY_CL(mbar_addr, phase) do {                                   \
    unsigned int _m = (mbar_addr), _ph = (phase), _d;                           \
    asm volatile("{\n\t.reg .pred p;\n\t"                                       \
        "mbarrier.try_wait.parity.acquire.cluster.shared::cta.b64 p, [%1], %2;\n\t" \
        "selp.b32 %0, 1, 0, p;\n\t}"                                            \
        : "=r"(_d) : "r"(_m), "r"(_ph) : "memory");                             \
    if (!_d) {                                                                  \
        asm volatile("{\n\t.reg .pred P1;\n\t"                                  \
            "W_%=:\n\t"                                                         \
            "mbarrier.try_wait.parity.acquire.cluster.shared::cta.b64 P1, [%0], %1, 0x989680;\n\t" \
            "@P1 bra.uni D_%=;\n\t"                                             \
            "bra.uni W_%=;\n\t"                                                 \
            "D_%=:\n\t}" :: "r"(_m), "r"(_ph) : "memory");                      \
    }                                                                           \
} while (0)

// ---------------------------------------------------------------------------
// GEMM: C[m,n] = epi( sum_k A[m,k]*Bw[n,k] + bias )   (both operands K-major)
// BM=BN=128, BK=16, 256 threads, 8x8 micro-tile via f32x2 packed FMA.
// Double-buffered smem: one __syncthreads per k-tile.
// EPI==0: + bias1[n] + bias2[n]      EPI==1: sigmoid(x + bias1[n])
// ---------------------------------------------------------------------------
template<int EPI>
__global__ void __launch_bounds__(256, 2)
gemm_nt(const float* __restrict__ A, const float* __restrict__ Bw,
        const float* __restrict__ bias1, const float* __restrict__ bias2,
        float* __restrict__ C, int M, int N, int K)
{
    __shared__ __align__(16) float As[2][16][132];
    __shared__ __align__(16) float Bs[2][16][132];
    const int tid = threadIdx.x;
    const int m0 = blockIdx.y << 7;
    const int n0 = blockIdx.x << 7;
    const int ar = tid >> 2;          // 0..63
    const int ac = (tid & 3) << 2;    // 0,4,8,12
    const float* Ag = A  + (size_t)(m0 + ar) * K + ac;
    const float* Bg = Bw + (size_t)(n0 + ar) * K + ac;
    const int tm = tid >> 4;          // 0..15 (row group of 8)
    const int tn = tid & 15;          // 0..15 (col group: tn*4 and tn*4+64)

    ull acc[4][8];
#pragma unroll
    for (int i = 0; i < 4; i++)
#pragma unroll
        for (int j = 0; j < 8; j++) acc[i][j] = 0ull;

    // prologue: tile 0 -> buffer 0
    float4 a0 = *(const float4*)(Ag);
    float4 a1 = *(const float4*)(Ag + (size_t)64 * K);
    float4 b0 = *(const float4*)(Bg);
    float4 b1 = *(const float4*)(Bg + (size_t)64 * K);
    int buf = 0;
    {
        As[0][ac + 0][ar]      = a0.x; As[0][ac + 1][ar]      = a0.y;
        As[0][ac + 2][ar]      = a0.z; As[0][ac + 3][ar]      = a0.w;
        As[0][ac + 0][ar + 64] = a1.x; As[0][ac + 1][ar + 64] = a1.y;
        As[0][ac + 2][ar + 64] = a1.z; As[0][ac + 3][ar + 64] = a1.w;
        Bs[0][ac + 0][ar]      = b0.x; Bs[0][ac + 1][ar]      = b0.y;
        Bs[0][ac + 2][ar]      = b0.z; Bs[0][ac + 3][ar]      = b0.w;
        Bs[0][ac + 0][ar + 64] = b1.x; Bs[0][ac + 1][ar + 64] = b1.y;
        Bs[0][ac + 2][ar + 64] = b1.z; Bs[0][ac + 3][ar + 64] = b1.w;
    }
    __syncthreads();

    for (int k0 = 0; k0 < K; k0 += 16) {
        const bool more = (k0 + 16) < K;
        if (more) {
            Ag += 16; Bg += 16;
            a0 = *(const float4*)(Ag);
            a1 = *(const float4*)(Ag + (size_t)64 * K);
            b0 = *(const float4*)(Bg);
            b1 = *(const float4*)(Bg + (size_t)64 * K);
        }
#pragma unroll
        for (int k = 0; k < 16; k++) {
            ulonglong2 aA = *(const ulonglong2*)&As[buf][k][tm * 8];
            ulonglong2 aB = *(const ulonglong2*)&As[buf][k][tm * 8 + 4];
            float4 bA = *(const float4*)&Bs[buf][k][tn * 4];
            float4 bB = *(const float4*)&Bs[buf][k][tn * 4 + 64];
            ull a2[4] = { aA.x, aA.y, aB.x, aB.y };
            ull bb[8] = { pack2(bA.x, bA.x), pack2(bA.y, bA.y),
                          pack2(bA.z, bA.z), pack2(bA.w, bA.w),
                          pack2(bB.x, bB.x), pack2(bB.y, bB.y),
                          pack2(bB.z, bB.z), pack2(bB.w, bB.w) };
#pragma unroll
            for (int j = 0; j < 8; j++)
#pragma unroll
                for (int i = 0; i < 4; i++)
                    acc[i][j] = fma2(a2[i], bb[j], acc[i][j]);
        }
        if (more) {
            int nb = buf ^ 1;
            As[nb][ac + 0][ar]      = a0.x; As[nb][ac + 1][ar]      = a0.y;
            As[nb][ac + 2][ar]      = a0.z; As[nb][ac + 3][ar]      = a0.w;
            As[nb][ac + 0][ar + 64] = a1.x; As[nb][ac + 1][ar + 64] = a1.y;
            As[nb][ac + 2][ar + 64] = a1.z; As[nb][ac + 3][ar + 64] = a1.w;
            Bs[nb][ac + 0][ar]      = b0.x; Bs[nb][ac + 1][ar]      = b0.y;
            Bs[nb][ac + 2][ar]      = b0.z; Bs[nb][ac + 3][ar]      = b0.w;
            Bs[nb][ac + 0][ar + 64] = b1.x; Bs[nb][ac + 1][ar + 64] = b1.y;
            Bs[nb][ac + 2][ar + 64] = b1.z; Bs[nb][ac + 3][ar + 64] = b1.w;
            __syncthreads();
            buf = nb;
        }
    }

    float bv[8];
#pragma unroll
    for (int j = 0; j < 4; j++) {
        bv[j]     = bias1[n0 + tn * 4 + j];
        bv[4 + j] = bias1[n0 + tn * 4 + 64 + j];
    }
    if (EPI == 0) {
#pragma unroll
        for (int j = 0; j < 4; j++) {
            bv[j]     += bias2[n0 + tn * 4 + j];
            bv[4 + j] += bias2[n0 + tn * 4 + 64 + j];
        }
    }
#pragma unroll
    for (int i2 = 0; i2 < 4; i2++) {
        float2 v[8];
#pragma unroll
        for (int j = 0; j < 8; j++) v[j] = unpack2(acc[i2][j]);
#pragma unroll
        for (int half = 0; half < 2; half++) {
            int m = m0 + tm * 8 + i2 * 2 + half;
            float r[8];
#pragma unroll
            for (int j = 0; j < 8; j++) {
                float x = (half ? v[j].y : v[j].x) + bv[j];
                if (EPI == 1) x = 1.0f / (1.0f + expf(-x));
                r[j] = x;
            }
            *(float4*)&C[(size_t)m * N + n0 + tn * 4]      = make_float4(r[0], r[1], r[2], r[3]);
            *(float4*)&C[(size_t)m * N + n0 + tn * 4 + 64] = make_float4(r[4], r[5], r[6], r[7]);
        }
    }
}

// ---------------------------------------------------------------------------
// Recurrence: 64 clusters of 2 CTAs, one batch element per cluster.
// CTA rank r owns output cols [r*128, r*128+128). Thread layout: col=tid>>1,
// j-half=tid&1 (partner = adjacent lane -> shfl reduction, no smem round-trip).
// W_hh half per CTA in registers (64 ull/thread). Per-step cross-CTA exchange
// via st.shared::cluster + mbarrier handshake (no barrier.cluster in the loop).
// ---------------------------------------------------------------------------
__global__ void __cluster_dims__(2, 1, 1) __launch_bounds__(256, 1)
rnn_scan(const float* __restrict__ W_hh, const float* __restrict__ prev,
         float* __restrict__ hn_out)
{
    __shared__ __align__(16) float h_sh[2][264];   // [buf][ (j>>7)*132 + (j&127) ]
    __shared__ __align__(8) unsigned long long mbar[2];
    const int tid = threadIdx.x;
    const int b = blockIdx.x >> 1;
    unsigned int rank;
    asm("mov.u32 %0, %%cluster_ctarank;" : "=r"(rank));
    const unsigned int peer = rank ^ 1u;
    const int jh    = tid & 1;         // which j-half this thread reduces
    const int col_l = tid >> 1;        // local output col 0..127
    const int col   = (int)rank * 128 + col_l;

    // This thread's 128 weights: W_hh[col][jh*128 .. jh*128+127] as 64 f32x2
    ull w2[64];
    {
        const ull* wrow = (const ull*)(W_hh + (size_t)col * NH + jh * 128);
#pragma unroll
        for (int q = 0; q < 64; q++) w2[q] = wrow[q];
    }

    if (tid == 0) {
        asm volatile("mbarrier.init.shared.b64 [%0], %1;" :: "r"(s2u(&mbar[0])), "r"(128u) : "memory");
        asm volatile("mbarrier.init.shared.b64 [%0], %1;" :: "r"(s2u(&mbar[1])), "r"(128u) : "memory");
    }
    // h0 (full vector, local copy in each CTA)
    h_sh[0][(tid >> 7) * 132 + (tid & 127)] = prev[b * NH + tid];
    __syncthreads();
    asm volatile("barrier.cluster.arrive.aligned;" ::: "memory");
    asm volatile("barrier.cluster.wait.aligned;"   ::: "memory");

    // Precomputed remote addresses (writer slot + peer's mbarriers)
    unsigned int remw[2], remmb[2], locmb[2];
    locmb[0] = s2u(&mbar[0]); locmb[1] = s2u(&mbar[1]);
    {
        unsigned int l0 = s2u(&h_sh[0][rank * 132 + col_l]);
        unsigned int l1 = s2u(&h_sh[1][rank * 132 + col_l]);
        asm("mapa.shared::cluster.u32 %0, %1, %2;" : "=r"(remw[0])  : "r"(l0),       "r"(peer));
        asm("mapa.shared::cluster.u32 %0, %1, %2;" : "=r"(remw[1])  : "r"(l1),       "r"(peer));
        asm("mapa.shared::cluster.u32 %0, %1, %2;" : "=r"(remmb[0]) : "r"(locmb[0]), "r"(peer));
        asm("mapa.shared::cluster.u32 %0, %1, %2;" : "=r"(remmb[1]) : "r"(locmb[1]), "r"(peer));
    }
    unsigned int ph0 = 0, ph1 = 0;

    const float* xrow  = g_xproj  + ((size_t)b * NT) * NH + col;
    float*       hidro = g_hidden + ((size_t)b * NT) * NH + col;
    float xp_next = (jh == 0) ? xrow[0] : 0.0f;

    int p = 0;
    for (int t = 0; t < NT; t++) {
        float xp = xp_next;
        if (jh == 0 && t + 1 < NT) xp_next = xrow[(size_t)(t + 1) * NH];  // prefetch

        const ulonglong2* h4 = (const ulonglong2*)&h_sh[p][jh * 132];
        ull a0 = 0ull, a1 = 0ull, a2 = 0ull, a3 = 0ull;   // 4 chains, depth 16
#pragma unroll
        for (int q = 0; q < 16; q++) {
            ulonglong2 u = h4[2 * q];
            ulonglong2 v = h4[2 * q + 1];
            a0 = fma2(w2[4 * q],     u.x, a0);
            a1 = fma2(w2[4 * q + 1], u.y, a1);
            a2 = fma2(w2[4 * q + 2], v.x, a2);
            a3 = fma2(w2[4 * q + 3], v.y, a3);
        }
        float2 f0 = unpack2(a0), f1 = unpack2(a1), f2 = unpack2(a2), f3 = unpack2(a3);
        float acc = ((f0.x + f0.y) + (f1.x + f1.y)) + ((f2.x + f2.y) + (f3.x + f3.y));
        float tot = acc + __shfl_xor_sync(0xffffffffu, acc, 1);

        const int nb = p ^ 1;
        if (jh == 0) {
            float h = fmaxf(tot + xp, 0.0f);
            h_sh[nb][rank * 132 + col_l] = h;              // local copy
            unsigned int hb = __float_as_uint(h);
            unsigned int ra = nb ? remw[1] : remw[0];
            asm volatile("st.shared::cluster.b32 [%0], %1;" :: "r"(ra), "r"(hb) : "memory");
            hidro[(size_t)t * NH] = fminf(h, 1.0f);        // capped lrelu (h>=0)
            if (t == NT - 1) hn_out[b * NH + col] = h;
            unsigned int rb = nb ? remmb[1] : remmb[0];
            asm volatile("mbarrier.arrive.release.cluster.shared::cluster.b64 _, [%0];"
                         :: "r"(rb) : "memory");
        }
        if (nb) { WAIT_PARITY_CL(locmb[1], ph1); ph1 ^= 1; }
        else    { WAIT_PARITY_CL(locmb[0], ph0); ph0 ^= 1; }
        __syncthreads();   // local-half writes visible to all local threads
        p = nb;
    }
    asm volatile("barrier.cluster.arrive.aligned;" ::: "memory");
    asm volatile("barrier.cluster.wait.aligned;"   ::: "memory");
}

// ---------------------------------------------------------------------------
extern "C" void kernel_launch(void* const* d_in, const int* in_sizes, int n_in,
                              void* d_out, int out_size)
{
    const float* sentence = (const float*)d_in[0];
    const float* prev     = (const float*)d_in[1];
    const float* W_ih     = (const float*)d_in[2];
    const float* b_ih     = (const float*)d_in[3];
    const float* W_hh     = (const float*)d_in[4];
    const float* b_hh     = (const float*)d_in[5];
    const float* W_out    = (const float*)d_in[6];
    const float* b_out    = (const float*)d_in[7];
    float* out = (float*)d_out;

    float* xproj = nullptr;
    float* hidden = nullptr;
    cudaGetSymbolAddress((void**)&xproj, g_xproj);
    cudaGetSymbolAddress((void**)&hidden, g_hidden);

    // Phase 1: x_proj = sentence @ W_ih^T + (b_ih + b_hh)
    gemm_nt<0><<<dim3(NH / 128, MR / 128), 256>>>(sentence, W_ih, b_ih, b_hh,
                                                  xproj, MR, NH, NV);
    // Phase 2: sequential scan; writes g_hidden and h_n (tail of d_out)
    rnn_scan<<<NB * 2, 256>>>(W_hh, prev, out + (size_t)MR * NO);
    // Phase 3: tags = sigmoid(hidden @ W_out^T + b_out)
    gemm_nt<1><<<dim3(NO / 128, MR / 128), 256>>>(hidden, W_out, b_out, nullptr,
                                                  out, MR, NO, NH);
}